// round 16
// baseline (speedup 1.0000x reference)
#include <cuda_runtime.h>
#include <cstdint>

#define BB 8
#define CC 192
#define HH 128
#define WW 256
#define HWSZ (HH*WW)

#define QHT 8
#define QWT 16
#define KC 32                 // channels per chunk
#define NCHUNK 6
#define THREADS 256

#define MPAD 136              // A row pad (words)
#define NPAD 200              // B row pad (words)
#define BWORDS (KC*NPAD)      // 6400 words per B buffer
#define AOFF (2*BWORDS)       // 12800
#define AWORDS (CC*MPAD)      // 26112
#define SMEM_BYTES ((AOFF + AWORDS)*4)   // 155648

__device__ __forceinline__ uint32_t smem_u32(const void* p) {
    return (uint32_t)__cvta_generic_to_shared(p);
}
__device__ __forceinline__ void cp_async16(uint32_t dst, const float* src, int srcsize) {
    asm volatile("cp.async.cg.shared.global [%0], [%1], 16, %2;\n"
                 :: "r"(dst), "l"(src), "r"(srcsize));
}
__device__ __forceinline__ void cp_commit() {
    asm volatile("cp.async.commit_group;\n" ::: "memory");
}
template<int N>
__device__ __forceinline__ void cp_wait_group() {
    asm volatile("cp.async.wait_group %0;\n" :: "n"(N) : "memory");
}
__device__ __forceinline__ uint32_t f2tf32(float f) {
    uint32_t r;
    asm("cvt.rna.tf32.f32 %0, %1;" : "=r"(r) : "f"(f));
    return r;
}
// D += A*B, m16n8k8 tf32 (base ISA)
__device__ __forceinline__ void mma_tf32(float (&d)[4],
    uint32_t a0, uint32_t a1, uint32_t a2, uint32_t a3,
    uint32_t b0, uint32_t b1) {
    asm volatile(
        "mma.sync.aligned.m16n8k8.row.col.f32.tf32.tf32.f32 "
        "{%0,%1,%2,%3}, {%4,%5,%6,%7}, {%8,%9}, {%0,%1,%2,%3};"
        : "+f"(d[0]), "+f"(d[1]), "+f"(d[2]), "+f"(d[3])
        : "r"(a0), "r"(a1), "r"(a2), "r"(a3), "r"(b0), "r"(b1));
}

// Stage one B chunk (pass p, chunk c): 1536 16B vectors, 6 per thread.
__device__ __forceinline__ void prefetchB(const float* __restrict__ x2,
    int b, int h0, int w0, int p, int c, uint32_t bbase, int tid) {
    #pragma unroll
    for (int k = 0; k < 6; ++k) {
        int t   = tid + k*THREADS;         // < 1536 exactly
        int chl = t / 48;
        int r   = t - 48*chl;
        int khl = r / 6;
        int v   = r - 6*khl;
        int gh  = h0 - 4 + 8*p + khl;
        int gw  = w0 - 4 + 4*v;
        int ok  = ((unsigned)gh < HH) && ((unsigned)gw <= WW-4);
        int ghc = min(max(gh, 0), HH-1);
        int gwc = min(max(gw, 0), WW-4);
        const float* src = x2 + (b*CC + c*KC + chl)*HWSZ + ghc*WW + gwc;
        uint32_t dst = bbase + (uint32_t)(chl*NPAD + khl*24 + 4*v)*4u;
        cp_async16(dst, src, ok ? 16 : 0);
    }
}

__global__ __launch_bounds__(THREADS, 1)
void costvol_mma_kernel(const float* __restrict__ x1,
                        const float* __restrict__ x2,
                        float* __restrict__ out) {
    extern __shared__ __align__(16) uint32_t smw[];
    const uint32_t sbase = smem_u32(smw);

    const int tid  = threadIdx.x;
    const int wid  = tid >> 5;        // warp -> qh row (M tile 16 = one qh)
    const int lane = tid & 31;
    const int gid  = lane >> 2;
    const int tig  = lane & 3;
    const int m0   = wid*16 + gid;

    const int b  = blockIdx.z;
    const int h0 = blockIdx.y * QHT;
    const int w0 = blockIdx.x * QWT;

    // ---- prologue: cp.async A (raw f32), then B chunks 0,1 of pass 0 ----
    #pragma unroll
    for (int k = 0; k < 24; ++k) {
        int t  = tid + k*THREADS;         // < 6144 exactly
        int ch = t >> 5;
        int mm = (t & 31) * 4;
        const float* src = x1 + (b*CC + ch)*HWSZ + (h0 + (mm >> 4))*WW + w0 + (mm & 15);
        cp_async16(sbase + (uint32_t)(AOFF + ch*MPAD + mm)*4u, src, 16);
    }
    cp_commit();
    prefetchB(x2, b, h0, w0, 0, 0, sbase + 0u,         tid); cp_commit();
    prefetchB(x2, b, h0, w0, 0, 1, sbase + BWORDS*4u,  tid); cp_commit();

    // A arrived -> convert to tf32 RNA in place
    cp_wait_group<2>();
    __syncthreads();
    #pragma unroll
    for (int k = 0; k < 24; ++k) {
        int t  = tid + k*THREADS;
        int ch = t >> 5;
        int mm = (t & 31) * 4;
        uint32_t* pa = smw + AOFF + ch*MPAD + mm;
        float4 v = *(float4*)pa;
        pa[0] = f2tf32(v.x); pa[1] = f2tf32(v.y);
        pa[2] = f2tf32(v.z); pa[3] = f2tf32(v.w);
    }

    float acc[24][4];
    #pragma unroll
    for (int nf = 0; nf < 24; ++nf)
        #pragma unroll
        for (int r = 0; r < 4; ++r) acc[nf][r] = 0.0f;

    const float inv81 = 1.0f / 81.0f;

    for (int p = 0; p < 2; ++p) {
        for (int c = 0; c < NCHUNK; ++c) {
            if (c < NCHUNK-1 || p == 0) cp_wait_group<1>();
            else                        cp_wait_group<0>();
            __syncthreads();

            // ---- convert this B buffer to tf32 (RNA) in place ----
            uint32_t* bb = smw + (c & 1)*BWORDS;
            #pragma unroll
            for (int k = 0; k < 25; ++k) {
                int t = tid + k*THREADS;          // 25*256 = 6400 = BWORDS
                bb[t] = f2tf32(__uint_as_float(bb[t]));
            }
            __syncthreads();

            // ---- MMA on buffer c&1 ----
            const uint32_t* bbuf = smw + (c & 1)*BWORDS;
            #pragma unroll
            for (int ks = 0; ks < 4; ++ks) {
                const int ka = c*KC + ks*8;
                uint32_t a0 = smw[AOFF + (ka+tig)*MPAD   + m0];
                uint32_t a1 = smw[AOFF + (ka+tig)*MPAD   + m0 + 8];
                uint32_t a2 = smw[AOFF + (ka+tig+4)*MPAD + m0];
                uint32_t a3 = smw[AOFF + (ka+tig+4)*MPAD + m0 + 8];
                #pragma unroll
                for (int nf = 0; nf < 24; ++nf) {
                    uint32_t b0 = bbuf[(ks*8+tig)*NPAD   + nf*8 + gid];
                    uint32_t b1 = bbuf[(ks*8+tig+4)*NPAD + nf*8 + gid];
                    mma_tf32(acc[nf], a0, a1, a2, a3, b0, b1);
                }
            }
            __syncthreads();

            if (c + 2 < NCHUNK) {
                prefetchB(x2, b, h0, w0, p, c+2, sbase + (uint32_t)(c&1)*BWORDS*4u, tid);
                cp_commit();
            } else if (p == 0) {
                prefetchB(x2, b, h0, w0, 1, c-4, sbase + (uint32_t)(c&1)*BWORDS*4u, tid);
                cp_commit();
            }
        }

        // ---- extraction for pass p ----
        // di = qh + 4 - (8p + kh)  ->  dip = wid + 8 - 8p - nf3
        // dj = qw + 4 - kw         ->  djp = qw + 8 - (rem0 + col)
        float* ob = out + (b*81)*HWSZ + (h0 + wid)*WW + w0;
        #pragma unroll
        for (int nf = 0; nf < 24; ++nf) {
            const int nf3  = nf / 3;          // kh_local (compile-time)
            const int rem0 = (nf % 3) * 8;    // kw base (compile-time)
            int dip = wid + 8 - 8*p - nf3;
            if ((unsigned)dip <= 8u) {
                #pragma unroll
                for (int r = 0; r < 4; ++r) {
                    int col = 2*tig + (r & 1);
                    int qw  = gid + ((r & 2) << 2);
                    int djp = qw + 8 - (rem0 + col);
                    if ((unsigned)djp <= 8u) {
                        int pr  = 9*dip + djp;
                        int idx = (pr >= 40) ? pr - 40 : pr + 41;
                        ob[idx*HWSZ + qw] = acc[nf][r] * inv81;
                    }
                }
            }
            #pragma unroll
            for (int r = 0; r < 4; ++r) acc[nf][r] = 0.0f;
        }
    }
}

extern "C" void kernel_launch(void* const* d_in, const int* in_sizes, int n_in,
                              void* d_out, int out_size) {
    const float* x1 = (const float*)d_in[0];
    const float* x2 = (const float*)d_in[1];
    float* out = (float*)d_out;
    cudaFuncSetAttribute(costvol_mma_kernel,
                         cudaFuncAttributeMaxDynamicSharedMemorySize, SMEM_BYTES);
    dim3 grid(WW/QWT, HH/QHT, BB);   // (16, 16, 8)
    dim3 block(THREADS);
    costvol_mma_kernel<<<grid, block, SMEM_BYTES>>>(x1, x2, out);
}

// round 17
// speedup vs baseline: 1.1351x; 1.1351x over previous
#include <cuda_runtime.h>
#include <cstdint>

#define BB 8
#define CC 192
#define HH 128
#define WW 256
#define HWSZ (HH*WW)

#define QHT 8
#define QWT 16
#define KC 32                 // channels per chunk
#define NCHUNK 6
#define THREADS 512           // 16 warps: 4M x 4N

#define MPAD 136              // A row pad (words)
#define NPAD 200              // B row pad (words)
#define BWORDS (KC*NPAD)      // 6400 words per B buffer
#define AOFF (2*BWORDS)       // 12800
#define AWORDS (CC*MPAD)      // 26112
#define SMEM_BYTES ((AOFF + AWORDS)*4)   // 155648

__device__ __forceinline__ uint32_t smem_u32(const void* p) {
    return (uint32_t)__cvta_generic_to_shared(p);
}
__device__ __forceinline__ void cp_async16(uint32_t dst, const float* src, int srcsize) {
    asm volatile("cp.async.cg.shared.global [%0], [%1], 16, %2;\n"
                 :: "r"(dst), "l"(src), "r"(srcsize));
}
__device__ __forceinline__ void cp_commit() {
    asm volatile("cp.async.commit_group;\n" ::: "memory");
}
template<int N>
__device__ __forceinline__ void cp_wait_group() {
    asm volatile("cp.async.wait_group %0;\n" :: "n"(N) : "memory");
}
__device__ __forceinline__ uint32_t f2tf32(float f) {
    uint32_t r;
    asm("cvt.rna.tf32.f32 %0, %1;" : "=r"(r) : "f"(f));
    return r;
}
__device__ __forceinline__ void mma_tf32(float (&d)[4],
    uint32_t a0, uint32_t a1, uint32_t a2, uint32_t a3,
    uint32_t b0, uint32_t b1) {
    asm volatile(
        "mma.sync.aligned.m16n8k8.row.col.f32.tf32.tf32.f32 "
        "{%0,%1,%2,%3}, {%4,%5,%6,%7}, {%8,%9}, {%0,%1,%2,%3};"
        : "+f"(d[0]), "+f"(d[1]), "+f"(d[2]), "+f"(d[3])
        : "r"(a0), "r"(a1), "r"(a2), "r"(a3), "r"(b0), "r"(b1));
}

// Stage one B chunk (pass p, chunk c): 1536 16B vectors, 3 per thread.
__device__ __forceinline__ void prefetchB(const float* __restrict__ x2,
    int b, int h0, int w0, int p, int c, uint32_t bbase, int tid) {
    #pragma unroll
    for (int k = 0; k < 3; ++k) {
        int t   = tid + k*THREADS;         // < 1536 exactly
        int chl = t / 48;
        int r   = t - 48*chl;
        int khl = r / 6;
        int v   = r - 6*khl;
        int gh  = h0 - 4 + 8*p + khl;
        int gw  = w0 - 4 + 4*v;
        int ok  = ((unsigned)gh < HH) && ((unsigned)gw <= WW-4);
        int ghc = min(max(gh, 0), HH-1);
        int gwc = min(max(gw, 0), WW-4);
        const float* src = x2 + (b*CC + c*KC + chl)*HWSZ + ghc*WW + gwc;
        uint32_t dst = bbase + (uint32_t)(chl*NPAD + khl*24 + 4*v)*4u;
        cp_async16(dst, src, ok ? 16 : 0);
    }
}

__global__ __launch_bounds__(THREADS, 1)
void costvol_mma_kernel(const float* __restrict__ x1,
                        const float* __restrict__ x2,
                        float* __restrict__ out) {
    extern __shared__ __align__(16) uint32_t smw[];
    const uint32_t sbase = smem_u32(smw);

    const int tid  = threadIdx.x;
    const int wid  = tid >> 5;        // 0..15
    const int lane = tid & 31;
    const int gid  = lane >> 2;
    const int tig  = lane & 3;
    const int mrow = wid & 3;         // M-warp row: m32 block
    const int ncol = wid >> 2;        // N-warp col: n48 block

    const int b  = blockIdx.z;
    const int h0 = blockIdx.y * QHT;
    const int w0 = blockIdx.x * QWT;

    // ---- prologue: cp.async A (raw f32), then B chunks 0,1 of pass 0 ----
    #pragma unroll
    for (int k = 0; k < 12; ++k) {
        int t  = tid + k*THREADS;         // < 6144 exactly
        int ch = t >> 5;
        int mm = (t & 31) * 4;
        const float* src = x1 + (b*CC + ch)*HWSZ + (h0 + (mm >> 4))*WW + w0 + (mm & 15);
        cp_async16(sbase + (uint32_t)(AOFF + ch*MPAD + mm)*4u, src, 16);
    }
    cp_commit();
    prefetchB(x2, b, h0, w0, 0, 0, sbase + 0u,         tid); cp_commit();
    prefetchB(x2, b, h0, w0, 0, 1, sbase + BWORDS*4u,  tid); cp_commit();

    // A arrived -> convert to tf32 RNA in place (vectorized)
    cp_wait_group<2>();
    __syncthreads();
    #pragma unroll
    for (int k = 0; k < 12; ++k) {
        int t  = tid + k*THREADS;
        int ch = t >> 5;
        int mm = (t & 31) * 4;
        uint32_t* pa = smw + AOFF + ch*MPAD + mm;
        float4 v = *(float4*)pa;
        pa[0] = f2tf32(v.x); pa[1] = f2tf32(v.y);
        pa[2] = f2tf32(v.z); pa[3] = f2tf32(v.w);
    }

    float acc[2][6][4];
    #pragma unroll
    for (int mt = 0; mt < 2; ++mt)
        #pragma unroll
        for (int nf = 0; nf < 6; ++nf)
            #pragma unroll
            for (int r = 0; r < 4; ++r) acc[mt][nf][r] = 0.0f;

    const float inv81 = 1.0f / 81.0f;

    for (int p = 0; p < 2; ++p) {
        for (int c = 0; c < NCHUNK; ++c) {
            if (c < NCHUNK-1 || p == 0) cp_wait_group<1>();
            else                        cp_wait_group<0>();
            __syncthreads();

            // ---- convert this B buffer to tf32 (RNA), uint4-vectorized ----
            uint32_t* bb = smw + (c & 1)*BWORDS;
            #pragma unroll
            for (int k = 0; k < 4; ++k) {
                int t = tid + k*THREADS;          // < 1600 uint4 = 6400 words
                if (t < BWORDS/4) {
                    float4 v = *(float4*)(bb + 4*t);
                    bb[4*t]   = f2tf32(v.x); bb[4*t+1] = f2tf32(v.y);
                    bb[4*t+2] = f2tf32(v.z); bb[4*t+3] = f2tf32(v.w);
                }
            }
            __syncthreads();

            // ---- MMA: warp tile m32 x n48 ----
            const uint32_t* bbuf = bb;
            #pragma unroll
            for (int ks = 0; ks < 4; ++ks) {
                const int ka = c*KC + ks*8;
                uint32_t a[2][4];
                #pragma unroll
                for (int mt = 0; mt < 2; ++mt) {
                    const int m0 = mrow*32 + mt*16 + gid;
                    a[mt][0] = smw[AOFF + (ka+tig)*MPAD   + m0];
                    a[mt][1] = smw[AOFF + (ka+tig)*MPAD   + m0 + 8];
                    a[mt][2] = smw[AOFF + (ka+tig+4)*MPAD + m0];
                    a[mt][3] = smw[AOFF + (ka+tig+4)*MPAD + m0 + 8];
                }
                #pragma unroll
                for (int nf = 0; nf < 6; ++nf) {
                    const int n0 = ncol*48 + nf*8 + gid;
                    uint32_t b0 = bbuf[(ks*8+tig)*NPAD   + n0];
                    uint32_t b1 = bbuf[(ks*8+tig+4)*NPAD + n0];
                    mma_tf32(acc[0][nf], a[0][0], a[0][1], a[0][2], a[0][3], b0, b1);
                    mma_tf32(acc[1][nf], a[1][0], a[1][1], a[1][2], a[1][3], b0, b1);
                }
            }
            __syncthreads();

            if (c + 2 < NCHUNK) {
                prefetchB(x2, b, h0, w0, p, c+2, sbase + (uint32_t)(c&1)*BWORDS*4u, tid);
                cp_commit();
            } else if (p == 0) {
                prefetchB(x2, b, h0, w0, 1, c-4, sbase + (uint32_t)(c&1)*BWORDS*4u, tid);
                cp_commit();
            }
        }

        // ---- extraction for pass p ----
        // kh_local = 2*ncol + (nf>=3); kw = nf*8 + col - 24*(nf>=3)
        // dip = qh + 8 - 8p - kh_local ; djp = qw + 8 - kw
        #pragma unroll
        for (int mt = 0; mt < 2; ++mt) {
            const int qh = mrow*2 + mt;
            float* ob = out + (b*81)*HWSZ + (h0 + qh)*WW + w0;
            #pragma unroll
            for (int nf = 0; nf < 6; ++nf) {
                const int khoff = (nf >= 3) ? 1 : 0;          // compile-time
                const int kwb   = nf*8 - 24*khoff;            // compile-time
                int dip = qh + 8 - 8*p - 2*ncol - khoff;
                if ((unsigned)dip <= 8u) {
                    #pragma unroll
                    for (int r = 0; r < 4; ++r) {
                        int col = 2*tig + (r & 1);
                        int qw  = gid + ((r & 2) << 2);
                        int djp = qw + 8 - (kwb + col);
                        if ((unsigned)djp <= 8u) {
                            int pr  = 9*dip + djp;
                            int idx = (pr >= 40) ? pr - 40 : pr + 41;
                            ob[idx*HWSZ + qw] = acc[mt][nf][r] * inv81;
                        }
                    }
                }
                #pragma unroll
                for (int r = 0; r < 4; ++r) acc[mt][nf][r] = 0.0f;
            }
        }
    }
}

extern "C" void kernel_launch(void* const* d_in, const int* in_sizes, int n_in,
                              void* d_out, int out_size) {
    const float* x1 = (const float*)d_in[0];
    const float* x2 = (const float*)d_in[1];
    float* out = (float*)d_out;
    cudaFuncSetAttribute(costvol_mma_kernel,
                         cudaFuncAttributeMaxDynamicSharedMemorySize, SMEM_BYTES);
    dim3 grid(WW/QWT, HH/QHT, BB);   // (16, 16, 8)
    dim3 block(THREADS);
    costvol_mma_kernel<<<grid, block, SMEM_BYTES>>>(x1, x2, out);
}